// round 1
// baseline (speedup 1.0000x reference)
#include <cuda_runtime.h>
#include <cstdint>

#define BB 8
#define NN 16384
#define FF 64
#define EE 262144
#define CC 10
#define BN_EPS 1e-5f

// ---------------- device scratch (no allocs allowed) ----------------
__device__ int   g_deg_out[BB * NN];
__device__ int   g_deg_in [BB * NN];
__device__ int   g_cursor [BB * NN];
__device__ float g_rs_out [BB * NN];
__device__ float g_rs_in  [BB * NN];
__device__ int   g_row_off[BB * (NN + 1)];
__device__ int   g_srt_src[BB * EE];
__device__ float g_h1[(size_t)BB * NN * FF];
__device__ float g_h2[(size_t)BB * NN * FF];
__device__ float g_bn_sum [2 * FF];
__device__ float g_bn_coef[2 * FF];   // [0..63]=scale, [64..127]=shift

// ---------------- kernels ----------------

__global__ void k_zero() {
    int i = blockIdx.x * blockDim.x + threadIdx.x;   // grid covers BB*NN exactly
    g_deg_out[i] = 0;
    g_deg_in[i]  = 0;
    g_cursor[i]  = 0;
    if (i < 2 * FF) g_bn_sum[i] = 0.0f;
}

__global__ void k_degree(const int* __restrict__ src, const int* __restrict__ dst) {
    int i = blockIdx.x * blockDim.x + threadIdx.x;   // BB*EE
    int b = i >> 18;                                  // EE = 2^18
    atomicAdd(&g_deg_out[b * NN + src[i]], 1);
    atomicAdd(&g_deg_in [b * NN + dst[i]], 1);
}

__global__ void k_rs() {
    int i = blockIdx.x * blockDim.x + threadIdx.x;   // BB*NN
    int dout = g_deg_out[i]; if (dout < 1) dout = 1;
    int din  = g_deg_in[i];  if (din  < 1) din  = 1;
    g_rs_out[i] = rsqrtf((float)dout);
    g_rs_in[i]  = rsqrtf((float)din);
}

// one block per batch, 1024 threads, 16 nodes per thread: exclusive scan of deg_in
__global__ void k_scan() {
    __shared__ int sh[1024];
    int b = blockIdx.x, t = threadIdx.x;
    int base = b * NN + t * 16;
    int loc[16];
    int sum = 0;
#pragma unroll
    for (int i = 0; i < 16; i++) { loc[i] = sum; sum += g_deg_in[base + i]; }
    sh[t] = sum;
    __syncthreads();
#pragma unroll
    for (int off = 1; off < 1024; off <<= 1) {
        int v = sh[t];
        int add = (t >= off) ? sh[t - off] : 0;
        __syncthreads();
        sh[t] = v + add;
        __syncthreads();
    }
    int excl = (t == 0) ? 0 : sh[t - 1];
    int ob = b * (NN + 1) + t * 16;
#pragma unroll
    for (int i = 0; i < 16; i++) g_row_off[ob + i] = excl + loc[i];
    if (t == 1023) g_row_off[b * (NN + 1) + NN] = sh[1023];
}

__global__ void k_fill(const int* __restrict__ src, const int* __restrict__ dst) {
    int i = blockIdx.x * blockDim.x + threadIdx.x;   // BB*EE
    int b = i >> 18;
    int d = dst[i];
    int p = atomicAdd(&g_cursor[b * NN + d], 1);
    g_srt_src[b * EE + g_row_off[b * (NN + 1) + d] + p] = src[i];
}

// Fused: CSR gather-aggregate (with both degree normalizations) + [32,64]x[64,64] GEMM + bias (+relu)
// 256 threads, 32 nodes per CTA. phase 0: x -> h1 (relu). phase 1: h1 -> h2.
__global__ __launch_bounds__(256) void k_conv(const float* __restrict__ xin,
                                              const float* __restrict__ W,
                                              const float* __restrict__ bias,
                                              int phase) {
    __shared__ float sW[64 * 64];
    __shared__ float sT[64][33];                      // [k][node], padded

    const float* in  = (phase == 0) ? xin : g_h1;
    float*       out = (phase == 0) ? g_h1 : g_h2;

    int t  = threadIdx.x;
    int cb = blockIdx.x;
    int b  = cb >> 9;                                 // 512 CTAs per batch
    int n0 = (cb & 511) << 5;

    for (int i = t; i < 64 * 64; i += 256) sW[i] = W[i];

    // ---- gather phase: 8 threads per node, 8 features each ----
    int nl = t >> 3;
    int f0 = (t & 7) << 3;
    int n  = n0 + nl;
    const float* inb = in + (size_t)b * NN * FF;
    const int*   ss  = g_srt_src + (size_t)b * EE;
    const float* rso = g_rs_out + b * NN;
    int r0 = g_row_off[b * (NN + 1) + n];
    int r1 = g_row_off[b * (NN + 1) + n + 1];

    float4 a0 = make_float4(0.f, 0.f, 0.f, 0.f);
    float4 a1 = make_float4(0.f, 0.f, 0.f, 0.f);
    for (int e = r0; e < r1; e++) {
        int s = __ldg(ss + e);
        float sc = __ldg(rso + s);
        const float4* p = (const float4*)(inb + (size_t)s * FF + f0);
        float4 v0 = __ldg(p);
        float4 v1 = __ldg(p + 1);
        a0.x = fmaf(v0.x, sc, a0.x); a0.y = fmaf(v0.y, sc, a0.y);
        a0.z = fmaf(v0.z, sc, a0.z); a0.w = fmaf(v0.w, sc, a0.w);
        a1.x = fmaf(v1.x, sc, a1.x); a1.y = fmaf(v1.y, sc, a1.y);
        a1.z = fmaf(v1.z, sc, a1.z); a1.w = fmaf(v1.w, sc, a1.w);
    }
    float si = g_rs_in[b * NN + n];
    a0.x *= si; a0.y *= si; a0.z *= si; a0.w *= si;
    a1.x *= si; a1.y *= si; a1.z *= si; a1.w *= si;

    sT[f0 + 0][nl] = a0.x; sT[f0 + 1][nl] = a0.y;
    sT[f0 + 2][nl] = a0.z; sT[f0 + 3][nl] = a0.w;
    sT[f0 + 4][nl] = a1.x; sT[f0 + 5][nl] = a1.y;
    sT[f0 + 6][nl] = a1.z; sT[f0 + 7][nl] = a1.w;
    __syncthreads();

    // ---- GEMM phase: each thread computes 2 nodes x 4 features ----
    int nn = (t >> 4) << 1;
    int q  = (t & 15) << 2;
    float4 c0 = make_float4(0.f, 0.f, 0.f, 0.f);
    float4 c1 = make_float4(0.f, 0.f, 0.f, 0.f);
#pragma unroll
    for (int k = 0; k < 64; k++) {
        float x0 = sT[k][nn];
        float x1 = sT[k][nn + 1];
        float4 w = *(const float4*)&sW[k * 64 + q];
        c0.x = fmaf(x0, w.x, c0.x); c0.y = fmaf(x0, w.y, c0.y);
        c0.z = fmaf(x0, w.z, c0.z); c0.w = fmaf(x0, w.w, c0.w);
        c1.x = fmaf(x1, w.x, c1.x); c1.y = fmaf(x1, w.y, c1.y);
        c1.z = fmaf(x1, w.z, c1.z); c1.w = fmaf(x1, w.w, c1.w);
    }
    float4 bv = __ldg((const float4*)(bias + q));
    c0.x += bv.x; c0.y += bv.y; c0.z += bv.z; c0.w += bv.w;
    c1.x += bv.x; c1.y += bv.y; c1.z += bv.z; c1.w += bv.w;
    if (phase == 0) {
        c0.x = fmaxf(c0.x, 0.f); c0.y = fmaxf(c0.y, 0.f);
        c0.z = fmaxf(c0.z, 0.f); c0.w = fmaxf(c0.w, 0.f);
        c1.x = fmaxf(c1.x, 0.f); c1.y = fmaxf(c1.y, 0.f);
        c1.z = fmaxf(c1.z, 0.f); c1.w = fmaxf(c1.w, 0.f);
    }
    *(float4*)(out + ((size_t)b * NN + n0 + nn)     * FF + q) = c0;
    *(float4*)(out + ((size_t)b * NN + n0 + nn + 1) * FF + q) = c1;
}

__global__ __launch_bounds__(256) void k_bnstats() {
    int tid = blockIdx.x * 256 + threadIdx.x;
    int stride = gridDim.x * 256;                    // multiple of 16
    const float4* h = (const float4*)g_h2;
    float4 s = make_float4(0.f, 0.f, 0.f, 0.f);
    float4 q = make_float4(0.f, 0.f, 0.f, 0.f);
    for (int i = tid; i < BB * NN * FF / 4; i += stride) {
        float4 v = __ldg(h + i);
        s.x += v.x; s.y += v.y; s.z += v.z; s.w += v.w;
        q.x = fmaf(v.x, v.x, q.x); q.y = fmaf(v.y, v.y, q.y);
        q.z = fmaf(v.z, v.z, q.z); q.w = fmaf(v.w, v.w, q.w);
    }
    int f0 = (tid & 15) * 4;
    __shared__ float sh[128];
    if (threadIdx.x < 128) sh[threadIdx.x] = 0.f;
    __syncthreads();
    atomicAdd(&sh[f0 + 0], s.x); atomicAdd(&sh[f0 + 1], s.y);
    atomicAdd(&sh[f0 + 2], s.z); atomicAdd(&sh[f0 + 3], s.w);
    atomicAdd(&sh[64 + f0 + 0], q.x); atomicAdd(&sh[64 + f0 + 1], q.y);
    atomicAdd(&sh[64 + f0 + 2], q.z); atomicAdd(&sh[64 + f0 + 3], q.w);
    __syncthreads();
    if (threadIdx.x < 128) atomicAdd(&g_bn_sum[threadIdx.x], sh[threadIdx.x]);
}

__global__ void k_bncoef(const float* __restrict__ gamma, const float* __restrict__ beta) {
    int f = threadIdx.x;                             // 64 threads
    const float inv_n = 1.0f / (float)(BB * NN);
    float mean = g_bn_sum[f] * inv_n;
    float var  = g_bn_sum[64 + f] * inv_n - mean * mean;
    float scale = gamma[f] * rsqrtf(var + BN_EPS);
    g_bn_coef[f]      = scale;
    g_bn_coef[64 + f] = beta[f] - mean * scale;
}

__global__ void k_outinit(const float* __restrict__ lin_b, float* __restrict__ out) {
    int t = threadIdx.x;                             // 80 threads
    out[t] = lin_b[t % CC];
}

// out[b][c] += sum_i (h2[b][i]*scale[f]+shift[f]) * lin_W[c][i]
__global__ __launch_bounds__(256) void k_final(const float* __restrict__ linW,
                                               float* __restrict__ out) {
    __shared__ float cf[128];
    if (threadIdx.x < 128) cf[threadIdx.x] = g_bn_coef[threadIdx.x];
    __syncthreads();

    int tid = blockIdx.x * 256 + threadIdx.x;
    int stride = gridDim.x * 256;                    // multiple of 16
    const int NI4 = NN * FF / 4;                     // 262144 float4 per batch row
    float acc[BB][CC];
#pragma unroll
    for (int b = 0; b < BB; b++)
#pragma unroll
        for (int c = 0; c < CC; c++) acc[b][c] = 0.f;

    const float4* h4 = (const float4*)g_h2;
    const float4* w4 = (const float4*)linW;
    for (int i = tid; i < NI4; i += stride) {
        int f0 = (i & 15) * 4;
        float4 sc  = *(const float4*)&cf[f0];
        float4 sh4 = *(const float4*)&cf[64 + f0];
        float4 hv[BB];
#pragma unroll
        for (int b = 0; b < BB; b++) {
            float4 v = __ldg(h4 + (size_t)b * NI4 + i);
            hv[b].x = fmaf(v.x, sc.x, sh4.x);
            hv[b].y = fmaf(v.y, sc.y, sh4.y);
            hv[b].z = fmaf(v.z, sc.z, sh4.z);
            hv[b].w = fmaf(v.w, sc.w, sh4.w);
        }
#pragma unroll
        for (int c = 0; c < CC; c++) {
            float4 w = __ldg(w4 + (size_t)c * NI4 + i);
#pragma unroll
            for (int b = 0; b < BB; b++) {
                float t0 = fmaf(hv[b].x, w.x, hv[b].y * w.y);
                float t1 = fmaf(hv[b].z, w.z, hv[b].w * w.w);
                acc[b][c] += t0 + t1;
            }
        }
    }
    // warp reduce, then cross-warp via shared, then 80 global atomics per CTA
#pragma unroll
    for (int b = 0; b < BB; b++)
#pragma unroll
        for (int c = 0; c < CC; c++)
#pragma unroll
            for (int off = 16; off > 0; off >>= 1)
                acc[b][c] += __shfl_xor_sync(0xFFFFFFFFu, acc[b][c], off);

    __shared__ float part[8][80];
    int w = threadIdx.x >> 5, lane = threadIdx.x & 31;
    if (lane == 0) {
#pragma unroll
        for (int b = 0; b < BB; b++)
#pragma unroll
            for (int c = 0; c < CC; c++) part[w][b * CC + c] = acc[b][c];
    }
    __syncthreads();
    int t = threadIdx.x;
    if (t < 80) {
        float s = 0.f;
#pragma unroll
        for (int ww = 0; ww < 8; ww++) s += part[ww][t];
        atomicAdd(&out[t], s);
    }
}

// ---------------- launch ----------------
extern "C" void kernel_launch(void* const* d_in, const int* in_sizes, int n_in,
                              void* d_out, int out_size) {
    const float* x     = (const float*)d_in[0];
    const int*   esrc  = (const int*)  d_in[1];
    const int*   edst  = (const int*)  d_in[2];
    const float* W1    = (const float*)d_in[3];
    const float* b1    = (const float*)d_in[4];
    const float* W2    = (const float*)d_in[5];
    const float* b2    = (const float*)d_in[6];
    const float* gamma = (const float*)d_in[7];
    const float* beta  = (const float*)d_in[8];
    const float* linW  = (const float*)d_in[9];
    const float* linb  = (const float*)d_in[10];
    float* out = (float*)d_out;

    k_zero  <<<(BB * NN) / 256, 256>>>();
    k_degree<<<(BB * EE) / 256, 256>>>(esrc, edst);
    k_rs    <<<(BB * NN) / 256, 256>>>();
    k_scan  <<<BB, 1024>>>();
    k_fill  <<<(BB * EE) / 256, 256>>>(esrc, edst);
    k_conv  <<<BB * (NN / 32), 256>>>(x, W1, b1, 0);
    k_conv  <<<BB * (NN / 32), 256>>>(x, W2, b2, 1);
    k_bnstats<<<256, 256>>>();
    k_bncoef<<<1, 64>>>(gamma, beta);
    k_outinit<<<1, 80>>>(linb, out);
    k_final <<<296, 256>>>(linW, out);
}

// round 3
// speedup vs baseline: 1.0350x; 1.0350x over previous
#include <cuda_runtime.h>
#include <cstdint>

#define BB 8
#define NN 16384
#define FF 64
#define EE 262144
#define CC 10
#define BN_EPS 1e-5f

// ---------------- device scratch (no allocs allowed) ----------------
__device__ int    g_deg_out[BB * NN];
__device__ int    g_deg_in [BB * NN];
__device__ int    g_cursor [BB * NN];
__device__ float  g_rs_out [BB * NN];
__device__ float  g_rs_in  [BB * NN];
__device__ int    g_row_off[BB * (NN + 1)];
__device__ float2 g_edge   [(size_t)BB * EE];     // {src_as_float_bits, rs_out[src]}
__device__ float  g_h1[(size_t)BB * NN * FF];
__device__ float  g_h2[(size_t)BB * NN * FF];
__device__ float  g_bn_sum [2 * FF];
__device__ float  g_bn_coef[2 * FF];              // [0..63]=scale, [64..127]=shift

// ---------------- kernels ----------------

__global__ void k_zero() {
    int i = blockIdx.x * blockDim.x + threadIdx.x;   // grid covers BB*NN exactly
    g_deg_out[i] = 0;
    g_deg_in[i]  = 0;
    if (i < 2 * FF) g_bn_sum[i] = 0.0f;
}

__global__ void k_degree(const int* __restrict__ src, const int* __restrict__ dst) {
    int i = blockIdx.x * blockDim.x + threadIdx.x;   // BB*EE
    int b = i >> 18;                                  // EE = 2^18
    atomicAdd(&g_deg_out[b * NN + src[i]], 1);
    atomicAdd(&g_deg_in [b * NN + dst[i]], 1);
}

// one block per batch, 1024 threads, 16 nodes/thread.
// Warp-shuffle exclusive scan of deg_in -> row_off, cursor(=row start), rs_in, rs_out.
__global__ __launch_bounds__(1024) void k_scan() {
    __shared__ int warpsum[32];
    int b = blockIdx.x, t = threadIdx.x;
    int lane = t & 31, wid = t >> 5;
    int base = b * NN + t * 16;
    int loc[16];
    int sum = 0;
#pragma unroll
    for (int i = 0; i < 16; i++) {
        int d = g_deg_in[base + i];
        loc[i] = sum; sum += d;
        g_rs_in[base + i] = rsqrtf((float)(d < 1 ? 1 : d));
        int dgo = g_deg_out[base + i];
        g_rs_out[base + i] = rsqrtf((float)(dgo < 1 ? 1 : dgo));
    }
    // inclusive warp scan of per-thread sums
    int v = sum;
#pragma unroll
    for (int off = 1; off < 32; off <<= 1) {
        int u = __shfl_up_sync(0xFFFFFFFFu, v, off);
        if (lane >= off) v += u;
    }
    if (lane == 31) warpsum[wid] = v;
    __syncthreads();
    if (wid == 0) {
        int w = warpsum[lane];
#pragma unroll
        for (int off = 1; off < 32; off <<= 1) {
            int u = __shfl_up_sync(0xFFFFFFFFu, w, off);
            if (lane >= off) w += u;
        }
        warpsum[lane] = w;
    }
    __syncthreads();
    int wbase = (wid == 0) ? 0 : warpsum[wid - 1];
    int excl  = wbase + v - sum;                      // exclusive prefix for this thread
    int ob = b * (NN + 1) + t * 16;
#pragma unroll
    for (int i = 0; i < 16; i++) {
        int o = excl + loc[i];
        g_row_off[ob + i] = o;
        g_cursor[base + i] = o;                       // bucket cursor starts at row start
    }
    if (t == 1023) g_row_off[b * (NN + 1) + NN] = excl + sum;
}

// bucket-fill sorted-by-dst edge list; store pre-scaled {src, rs_out[src]} pairs
__global__ void k_fill(const int* __restrict__ src, const int* __restrict__ dst) {
    int i = blockIdx.x * blockDim.x + threadIdx.x;   // BB*EE
    int b = i >> 18;
    int s = src[i];
    int d = dst[i];
    int pos = atomicAdd(&g_cursor[b * NN + d], 1);
    float sc = __ldg(&g_rs_out[b * NN + s]);
    g_edge[(size_t)b * EE + pos] = make_float2(__int_as_float(s), sc);
}

// Fused: CSR gather-aggregate + [32,64]x[64,64] GEMM + bias (+relu)
// 256 threads, 32 nodes per CTA. phase 0: x -> h1 (relu). phase 1: h1 -> h2.
__global__ __launch_bounds__(256) void k_conv(const float* __restrict__ xin,
                                              const float* __restrict__ W,
                                              const float* __restrict__ bias,
                                              int phase) {
    __shared__ float sW[64 * 64];
    __shared__ float sT[64][33];                      // [k][node], padded

    const float* in  = (phase == 0) ? xin : g_h1;
    float*       out = (phase == 0) ? g_h1 : g_h2;

    int t  = threadIdx.x;
    int cb = blockIdx.x;
    int b  = cb >> 9;                                 // 512 CTAs per batch
    int n0 = (cb & 511) << 5;

    for (int i = t; i < 64 * 64; i += 256) sW[i] = W[i];

    // ---- gather: 8 threads per node, 8 features each; pre-scaled edge pairs ----
    int nl = t >> 3;
    int f0 = (t & 7) << 3;
    int n  = n0 + nl;
    const float*  inb = in + (size_t)b * NN * FF;
    const float2* ep  = g_edge + (size_t)b * EE;
    int r0 = g_row_off[b * (NN + 1) + n];
    int r1 = g_row_off[b * (NN + 1) + n + 1];

    float4 a0 = make_float4(0.f, 0.f, 0.f, 0.f);
    float4 a1 = make_float4(0.f, 0.f, 0.f, 0.f);
    int e = r0;
    for (; e + 2 <= r1; e += 2) {
        float2 p0 = __ldg(ep + e);
        float2 p1 = __ldg(ep + e + 1);
        const float4* q0 = (const float4*)(inb + (size_t)__float_as_int(p0.x) * FF + f0);
        const float4* q1 = (const float4*)(inb + (size_t)__float_as_int(p1.x) * FF + f0);
        float4 v0 = __ldg(q0), v1 = __ldg(q0 + 1);
        float4 u0 = __ldg(q1), u1 = __ldg(q1 + 1);
        a0.x = fmaf(v0.x, p0.y, a0.x); a0.y = fmaf(v0.y, p0.y, a0.y);
        a0.z = fmaf(v0.z, p0.y, a0.z); a0.w = fmaf(v0.w, p0.y, a0.w);
        a1.x = fmaf(v1.x, p0.y, a1.x); a1.y = fmaf(v1.y, p0.y, a1.y);
        a1.z = fmaf(v1.z, p0.y, a1.z); a1.w = fmaf(v1.w, p0.y, a1.w);
        a0.x = fmaf(u0.x, p1.y, a0.x); a0.y = fmaf(u0.y, p1.y, a0.y);
        a0.z = fmaf(u0.z, p1.y, a0.z); a0.w = fmaf(u0.w, p1.y, a0.w);
        a1.x = fmaf(u1.x, p1.y, a1.x); a1.y = fmaf(u1.y, p1.y, a1.y);
        a1.z = fmaf(u1.z, p1.y, a1.z); a1.w = fmaf(u1.w, p1.y, a1.w);
    }
    if (e < r1) {
        float2 p0 = __ldg(ep + e);
        const float4* q0 = (const float4*)(inb + (size_t)__float_as_int(p0.x) * FF + f0);
        float4 v0 = __ldg(q0), v1 = __ldg(q0 + 1);
        a0.x = fmaf(v0.x, p0.y, a0.x); a0.y = fmaf(v0.y, p0.y, a0.y);
        a0.z = fmaf(v0.z, p0.y, a0.z); a0.w = fmaf(v0.w, p0.y, a0.w);
        a1.x = fmaf(v1.x, p0.y, a1.x); a1.y = fmaf(v1.y, p0.y, a1.y);
        a1.z = fmaf(v1.z, p0.y, a1.z); a1.w = fmaf(v1.w, p0.y, a1.w);
    }
    float si = g_rs_in[b * NN + n];
    a0.x *= si; a0.y *= si; a0.z *= si; a0.w *= si;
    a1.x *= si; a1.y *= si; a1.z *= si; a1.w *= si;

    sT[f0 + 0][nl] = a0.x; sT[f0 + 1][nl] = a0.y;
    sT[f0 + 2][nl] = a0.z; sT[f0 + 3][nl] = a0.w;
    sT[f0 + 4][nl] = a1.x; sT[f0 + 5][nl] = a1.y;
    sT[f0 + 6][nl] = a1.z; sT[f0 + 7][nl] = a1.w;
    __syncthreads();

    // ---- GEMM: each thread computes 2 nodes x 4 features ----
    int nn = (t >> 4) << 1;
    int q  = (t & 15) << 2;
    float4 c0 = make_float4(0.f, 0.f, 0.f, 0.f);
    float4 c1 = make_float4(0.f, 0.f, 0.f, 0.f);
#pragma unroll
    for (int k = 0; k < 64; k++) {
        float x0 = sT[k][nn];
        float x1 = sT[k][nn + 1];
        float4 w = *(const float4*)&sW[k * 64 + q];
        c0.x = fmaf(x0, w.x, c0.x); c0.y = fmaf(x0, w.y, c0.y);
        c0.z = fmaf(x0, w.z, c0.z); c0.w = fmaf(x0, w.w, c0.w);
        c1.x = fmaf(x1, w.x, c1.x); c1.y = fmaf(x1, w.y, c1.y);
        c1.z = fmaf(x1, w.z, c1.z); c1.w = fmaf(x1, w.w, c1.w);
    }
    float4 bv = __ldg((const float4*)(bias + q));
    c0.x += bv.x; c0.y += bv.y; c0.z += bv.z; c0.w += bv.w;
    c1.x += bv.x; c1.y += bv.y; c1.z += bv.z; c1.w += bv.w;
    if (phase == 0) {
        c0.x = fmaxf(c0.x, 0.f); c0.y = fmaxf(c0.y, 0.f);
        c0.z = fmaxf(c0.z, 0.f); c0.w = fmaxf(c0.w, 0.f);
        c1.x = fmaxf(c1.x, 0.f); c1.y = fmaxf(c1.y, 0.f);
        c1.w = fmaxf(c1.w, 0.f); c1.z = fmaxf(c1.z, 0.f);
    }
    *(float4*)(out + ((size_t)b * NN + n0 + nn)     * FF + q) = c0;
    *(float4*)(out + ((size_t)b * NN + n0 + nn + 1) * FF + q) = c1;
}

__global__ __launch_bounds__(256) void k_bnstats() {
    int tid = blockIdx.x * 256 + threadIdx.x;
    int stride = gridDim.x * 256;                    // multiple of 16
    const float4* h = (const float4*)g_h2;
    float4 s = make_float4(0.f, 0.f, 0.f, 0.f);
    float4 q = make_float4(0.f, 0.f, 0.f, 0.f);
    for (int i = tid; i < BB * NN * FF / 4; i += stride) {
        float4 v = __ldg(h + i);
        s.x += v.x; s.y += v.y; s.z += v.z; s.w += v.w;
        q.x = fmaf(v.x, v.x, q.x); q.y = fmaf(v.y, v.y, q.y);
        q.z = fmaf(v.z, v.z, q.z); q.w = fmaf(v.w, v.w, q.w);
    }
    int f0 = (tid & 15) * 4;
    __shared__ float sh[128];
    if (threadIdx.x < 128) sh[threadIdx.x] = 0.f;
    __syncthreads();
    atomicAdd(&sh[f0 + 0], s.x); atomicAdd(&sh[f0 + 1], s.y);
    atomicAdd(&sh[f0 + 2], s.z); atomicAdd(&sh[f0 + 3], s.w);
    atomicAdd(&sh[64 + f0 + 0], q.x); atomicAdd(&sh[64 + f0 + 1], q.y);
    atomicAdd(&sh[64 + f0 + 2], q.z); atomicAdd(&sh[64 + f0 + 3], q.w);
    __syncthreads();
    if (threadIdx.x < 128) atomicAdd(&g_bn_sum[threadIdx.x], sh[threadIdx.x]);
}

__global__ void k_bncoef(const float* __restrict__ gamma, const float* __restrict__ beta) {
    int f = threadIdx.x;                             // 64 threads
    const float inv_n = 1.0f / (float)(BB * NN);
    float mean = g_bn_sum[f] * inv_n;
    float var  = g_bn_sum[64 + f] * inv_n - mean * mean;
    float scale = gamma[f] * rsqrtf(var + BN_EPS);
    g_bn_coef[f]      = scale;
    g_bn_coef[64 + f] = beta[f] - mean * scale;
}

__global__ void k_outinit(const float* __restrict__ lin_b, float* __restrict__ out) {
    int t = threadIdx.x;                             // 80 threads
    out[t] = lin_b[t % CC];
}

// out[b][c] += sum_i (h2[b][i]*scale[f]+shift[f]) * lin_W[c][i]
__global__ __launch_bounds__(256) void k_final(const float* __restrict__ linW,
                                               float* __restrict__ out) {
    __shared__ float cf[128];
    if (threadIdx.x < 128) cf[threadIdx.x] = g_bn_coef[threadIdx.x];
    __syncthreads();

    int tid = blockIdx.x * 256 + threadIdx.x;
    int stride = gridDim.x * 256;                    // multiple of 16
    const int NI4 = NN * FF / 4;                     // 262144 float4 per batch row
    float acc[BB][CC];
#pragma unroll
    for (int b = 0; b < BB; b++)
#pragma unroll
        for (int c = 0; c < CC; c++) acc[b][c] = 0.f;

    const float4* h4 = (const float4*)g_h2;
    const float4* w4 = (const float4*)linW;
    for (int i = tid; i < NI4; i += stride) {
        int f0 = (i & 15) * 4;
        float4 sc  = *(const float4*)&cf[f0];
        float4 sh4 = *(const float4*)&cf[64 + f0];
        float4 hv[BB];
#pragma unroll
        for (int b = 0; b < BB; b++) {
            float4 v = __ldg(h4 + (size_t)b * NI4 + i);
            hv[b].x = fmaf(v.x, sc.x, sh4.x);
            hv[b].y = fmaf(v.y, sc.y, sh4.y);
            hv[b].z = fmaf(v.z, sc.z, sh4.z);
            hv[b].w = fmaf(v.w, sc.w, sh4.w);
        }
#pragma unroll
        for (int c = 0; c < CC; c++) {
            float4 w = __ldg(w4 + (size_t)c * NI4 + i);
#pragma unroll
            for (int b = 0; b < BB; b++) {
                float t0 = fmaf(hv[b].x, w.x, hv[b].y * w.y);
                float t1 = fmaf(hv[b].z, w.z, hv[b].w * w.w);
                acc[b][c] += t0 + t1;
            }
        }
    }
#pragma unroll
    for (int b = 0; b < BB; b++)
#pragma unroll
        for (int c = 0; c < CC; c++)
#pragma unroll
            for (int off = 16; off > 0; off >>= 1)
                acc[b][c] += __shfl_xor_sync(0xFFFFFFFFu, acc[b][c], off);

    __shared__ float part[8][80];
    int w = threadIdx.x >> 5, lane = threadIdx.x & 31;
    if (lane == 0) {
#pragma unroll
        for (int b = 0; b < BB; b++)
#pragma unroll
            for (int c = 0; c < CC; c++) part[w][b * CC + c] = acc[b][c];
    }
    __syncthreads();
    int t = threadIdx.x;
    if (t < 80) {
        float s = 0.f;
#pragma unroll
        for (int ww = 0; ww < 8; ww++) s += part[ww][t];
        atomicAdd(&out[t], s);
    }
}

// ---------------- launch ----------------
extern "C" void kernel_launch(void* const* d_in, const int* in_sizes, int n_in,
                              void* d_out, int out_size) {
    const float* x     = (const float*)d_in[0];
    const int*   esrc  = (const int*)  d_in[1];
    const int*   edst  = (const int*)  d_in[2];
    const float* W1    = (const float*)d_in[3];
    const float* b1    = (const float*)d_in[4];
    const float* W2    = (const float*)d_in[5];
    const float* b2    = (const float*)d_in[6];
    const float* gamma = (const float*)d_in[7];
    const float* beta  = (const float*)d_in[8];
    const float* linW  = (const float*)d_in[9];
    const float* linb  = (const float*)d_in[10];
    float* out = (float*)d_out;

    k_zero   <<<(BB * NN) / 256, 256>>>();
    k_degree <<<(BB * EE) / 256, 256>>>(esrc, edst);
    k_scan   <<<BB, 1024>>>();
    k_fill   <<<(BB * EE) / 256, 256>>>(esrc, edst);
    k_conv   <<<BB * (NN / 32), 256>>>(x, W1, b1, 0);
    k_conv   <<<BB * (NN / 32), 256>>>(x, W2, b2, 1);
    k_bnstats<<<256, 256>>>();
    k_bncoef <<<1, 64>>>(gamma, beta);
    k_outinit<<<1, 80>>>(linb, out);
    k_final  <<<296, 256>>>(linW, out);
}